// round 1
// baseline (speedup 1.0000x reference)
#include <cuda_runtime.h>
#include <cuda_bf16.h>
#include <math.h>

#define Bn 16
#define Cc 128
#define Pp 48
#define Nn (Pp*Pp)        // 2304
#define C8v 16            // C/8
#define BCN ((long)Bn*Cc*Nn)

// ---------------- scratch (device globals; no allocation allowed) ----------------
__device__ float g_bnA[Bn*Cc*Nn];     // BN output / TM input
__device__ float g_hid[Bn*Cc*Nn];     // TM hidden
__device__ float g_feat[Bn*Cc*Nn];    // features
__device__ float g_q[Bn*C8v*Nn];
__device__ float g_k[Bn*C8v*Nn];
__device__ float g_v[Bn*Cc*Nn];
__device__ float g_E[(long)Bn*Nn*Nn]; // 340 MB energy
__device__ float g_V[Bn*Cc*Nn];
__device__ float g_T[Bn*Cc*Nn];
__device__ float g_res[Bn*Cc*Nn];
__device__ float g_scale[Cc], g_shift[Cc];

// ---------------- BN: per-channel batch stats over (B,H,W) ----------------
__global__ void bn_stats(const float* __restrict__ x, const float* __restrict__ g,
                         const float* __restrict__ b, float* __restrict__ scale,
                         float* __restrict__ shift) {
    int c = blockIdx.x;
    int tid = threadIdx.x;
    double s = 0.0, sq = 0.0;
    for (int idx = tid; idx < Bn*Nn; idx += blockDim.x) {
        int bb = idx / Nn, n = idx - bb*Nn;
        float v = x[((long)bb*Cc + c)*Nn + n];
        s += v; sq += (double)v * v;
    }
    __shared__ double sh_s[256], sh_q[256];
    sh_s[tid] = s; sh_q[tid] = sq; __syncthreads();
    for (int off = 128; off; off >>= 1) {
        if (tid < off) { sh_s[tid] += sh_s[tid+off]; sh_q[tid] += sh_q[tid+off]; }
        __syncthreads();
    }
    if (tid == 0) {
        double inv = 1.0 / (double)(Bn*Nn);
        double mean = sh_s[0] * inv;
        double var  = sh_q[0] * inv - mean*mean;
        float sc = g[c] * rsqrtf((float)var + 1e-5f);
        scale[c] = sc;
        shift[c] = b[c] - (float)mean * sc;
    }
}

__global__ void bn_apply(const float* __restrict__ x, const float* __restrict__ scale,
                         const float* __restrict__ shift, float* __restrict__ y) {
    long i = (long)blockIdx.x * blockDim.x + threadIdx.x;
    if (i < BCN) {
        int c = (int)((i / Nn) % Cc);
        y[i] = x[i] * scale[c] + shift[c];
    }
}

// ---------------- generic tiled SGEMM ----------------
// C[m,n] = sum_k A[m,k] * B[?, ?] (+bias) (relu?)
//   A: M x K row-major (lda = K), batch stride sA
//   TRANSB=true : B is Nd x K row-major (ldb = K)     -> C = A @ B^T
//   TRANSB=false: B is K x Nd row-major (ldb = Nd)    -> C = A @ B
//                 with K-concat: rows [0,K1) from B1, rows [K1,K) from B2
//   BIASROW: bias indexed by m (out channel); else by n (out dim)
#define GBM 128
#define GBN 128
#define GBK 16

template<bool TRANSB, bool BIASROW, bool RELU>
__global__ __launch_bounds__(256, 1)
void gemm_kernel(const float* __restrict__ A,
                 const float* __restrict__ B1, const float* __restrict__ B2, int K1,
                 const float* __restrict__ bias, float* __restrict__ C,
                 int M, int Nd, int K, long sA, long sB, long sC) {
    __shared__ float As[GBK][GBM];
    __shared__ float Bs[GBK][GBN];
    int tid = threadIdx.x;
    int m0 = blockIdx.y * GBM;
    int n0 = blockIdx.x * GBN;
    long zb = blockIdx.z;
    const float* Ab  = A  + zb*sA;
    const float* B1b = B1 + zb*sB;
    const float* B2b = B2 + zb*sB;

    float acc[8][8];
#pragma unroll
    for (int i = 0; i < 8; i++)
#pragma unroll
        for (int j = 0; j < 8; j++) acc[i][j] = 0.f;

    int ar = tid >> 2;          // 0..63
    int ac = (tid & 3) * 4;     // 0,4,8,12
    int tm = (tid >> 4) * 8;
    int tn = (tid & 15) * 8;

    for (int k0 = 0; k0 < K; k0 += GBK) {
        // ---- load A tile (128 x 16), store transposed As[k][m]
#pragma unroll
        for (int r = 0; r < 2; r++) {
            int row = ar + 64*r;
            float4 av = *reinterpret_cast<const float4*>(Ab + (long)(m0+row)*K + k0 + ac);
            As[ac+0][row] = av.x; As[ac+1][row] = av.y;
            As[ac+2][row] = av.z; As[ac+3][row] = av.w;
        }
        // ---- load B tile
        if (TRANSB) {
#pragma unroll
            for (int r = 0; r < 2; r++) {
                int row = ar + 64*r;  // n index
                float4 bv = *reinterpret_cast<const float4*>(B1b + (long)(n0+row)*K + k0 + ac);
                Bs[ac+0][row] = bv.x; Bs[ac+1][row] = bv.y;
                Bs[ac+2][row] = bv.z; Bs[ac+3][row] = bv.w;
            }
        } else {
#pragma unroll
            for (int r = 0; r < 2; r++) {
                int s  = tid + 256*r;       // 512 float4 slots
                int kk = s >> 5;            // 0..15
                int nq = (s & 31) * 4;      // 0..124
                int kg = k0 + kk;
                const float* Bp = (kg < K1) ? (B1b + (long)kg*Nd)
                                            : (B2b + (long)(kg-K1)*Nd);
                *reinterpret_cast<float4*>(&Bs[kk][nq]) =
                    *reinterpret_cast<const float4*>(Bp + n0 + nq);
            }
        }
        __syncthreads();
        // ---- compute
#pragma unroll
        for (int kk = 0; kk < GBK; kk++) {
            float a[8], b[8];
            float4 a0 = *reinterpret_cast<const float4*>(&As[kk][tm]);
            float4 a1 = *reinterpret_cast<const float4*>(&As[kk][tm+4]);
            float4 b0 = *reinterpret_cast<const float4*>(&Bs[kk][tn]);
            float4 b1 = *reinterpret_cast<const float4*>(&Bs[kk][tn+4]);
            a[0]=a0.x;a[1]=a0.y;a[2]=a0.z;a[3]=a0.w;a[4]=a1.x;a[5]=a1.y;a[6]=a1.z;a[7]=a1.w;
            b[0]=b0.x;b[1]=b0.y;b[2]=b0.z;b[3]=b0.w;b[4]=b1.x;b[5]=b1.y;b[6]=b1.z;b[7]=b1.w;
#pragma unroll
            for (int i = 0; i < 8; i++)
#pragma unroll
                for (int j = 0; j < 8; j++)
                    acc[i][j] = fmaf(a[i], b[j], acc[i][j]);
        }
        __syncthreads();
    }
    // ---- epilogue
    int gm = m0 + tm, gn = n0 + tn;
#pragma unroll
    for (int i = 0; i < 8; i++) {
#pragma unroll
        for (int j = 0; j < 8; j++) {
            float v = acc[i][j];
            if (bias) v += BIASROW ? bias[gm+i] : bias[gn+j];
            if (RELU) v = fmaxf(v, 0.f);
            C[zb*sC + (long)(gm+i)*Nd + gn + j] = v;
        }
    }
}

// ---------------- q & k projection (C8=16 outputs each) ----------------
__global__ __launch_bounds__(256)
void qk_kernel(const float* __restrict__ feat,
               const float* __restrict__ qw, const float* __restrict__ qb,
               const float* __restrict__ kw, const float* __restrict__ kb,
               float* __restrict__ q, float* __restrict__ k) {
    __shared__ float wq[C8v*Cc], wk[C8v*Cc];
    int tid = threadIdx.x;
    for (int i = tid; i < C8v*Cc; i += 256) { wq[i] = qw[i]; wk[i] = kw[i]; }
    __syncthreads();
    int b = blockIdx.y;
    int n = blockIdx.x * 256 + tid;
    const float* f = feat + (long)b*Cc*Nn + n;
    float aq[C8v], ak[C8v];
#pragma unroll
    for (int o = 0; o < C8v; o++) { aq[o] = qb[o]; ak[o] = kb[o]; }
    for (int c = 0; c < Cc; c++) {
        float fv = f[(long)c*Nn];
#pragma unroll
        for (int o = 0; o < C8v; o++) {
            aq[o] = fmaf(wq[o*Cc+c], fv, aq[o]);
            ak[o] = fmaf(wk[o*Cc+c], fv, ak[o]);
        }
    }
#pragma unroll
    for (int o = 0; o < C8v; o++) {
        q[((long)b*C8v+o)*Nn + n] = aq[o];
        k[((long)b*C8v+o)*Nn + n] = ak[o];
    }
}

// ---------------- energy: S[b,i,j] = sum_c K[b,c,i]*Q[b,c,j] / sqrt(C) ----------------
__global__ __launch_bounds__(256)
void energy_kernel(const float* __restrict__ K_, const float* __restrict__ Q_,
                   float* __restrict__ E) {
    __shared__ float ks[C8v][64], qs[C8v][64];
    int b  = blockIdx.z;
    int i0 = blockIdx.y * 64, j0 = blockIdx.x * 64;
    int tid = threadIdx.x;
    const float* Kb = K_ + (long)b*C8v*Nn;
    const float* Qb = Q_ + (long)b*C8v*Nn;
    for (int s = tid; s < C8v*64; s += 256) {
        int c = s >> 6, x = s & 63;
        ks[c][x] = Kb[(long)c*Nn + i0 + x];
        qs[c][x] = Qb[(long)c*Nn + j0 + x];
    }
    __syncthreads();
    int ri = (tid >> 4) * 4, rj = (tid & 15) * 4;
    float acc[4][4] = {};
#pragma unroll
    for (int c = 0; c < C8v; c++) {
        float a[4], bb[4];
#pragma unroll
        for (int i = 0; i < 4; i++) a[i]  = ks[c][ri+i];
#pragma unroll
        for (int j = 0; j < 4; j++) bb[j] = qs[c][rj+j];
#pragma unroll
        for (int i = 0; i < 4; i++)
#pragma unroll
            for (int j = 0; j < 4; j++)
                acc[i][j] = fmaf(a[i], bb[j], acc[i][j]);
    }
    const float sc = 0.08838834764831845f;  // 1/sqrt(128)
    float* Eb = E + ((long)b*Nn + i0) * Nn + j0;
#pragma unroll
    for (int i = 0; i < 4; i++)
#pragma unroll
        for (int j = 0; j < 4; j++)
            Eb[(long)(ri+i)*Nn + rj + j] = acc[i][j] * sc;
}

// ---------------- row softmax over j (N=2304, 256 threads, 9 per thread) ----------------
__global__ __launch_bounds__(256)
void softmax_rows(float* __restrict__ E) {
    const int T = 256, PER = Nn / T;  // 9
    long row = blockIdx.x;
    float* p = E + row * (long)Nn;
    int tid = threadIdx.x;
    float v[PER];
    float m = -1e30f;
#pragma unroll
    for (int i = 0; i < PER; i++) { v[i] = p[tid + i*T]; m = fmaxf(m, v[i]); }
    __shared__ float red[8];
    __shared__ float bc;
#pragma unroll
    for (int o = 16; o; o >>= 1) m = fmaxf(m, __shfl_xor_sync(0xffffffffu, m, o));
    if ((tid & 31) == 0) red[tid >> 5] = m;
    __syncthreads();
    if (tid == 0) {
        float t = red[0];
        for (int i = 1; i < 8; i++) t = fmaxf(t, red[i]);
        bc = t;
    }
    __syncthreads();
    m = bc;
    float s = 0.f;
#pragma unroll
    for (int i = 0; i < PER; i++) { v[i] = __expf(v[i] - m); s += v[i]; }
#pragma unroll
    for (int o = 16; o; o >>= 1) s += __shfl_xor_sync(0xffffffffu, s, o);
    if ((tid & 31) == 0) red[tid >> 5] = s;
    __syncthreads();
    if (tid == 0) {
        float t = 0.f;
        for (int i = 0; i < 8; i++) t += red[i];
        bc = 1.f / t;
    }
    __syncthreads();
    float inv = bc;
#pragma unroll
    for (int i = 0; i < PER; i++) p[tid + i*T] = v[i] * inv;
}

// ---------------- launcher ----------------
extern "C" void kernel_launch(void* const* d_in, const int* in_sizes, int n_in,
                              void* d_out, int out_size) {
    const float* front_x = (const float*)d_in[0];
    const float* bn1_g = (const float*)d_in[1];
    const float* bn1_b = (const float*)d_in[2];
    const float* tm1_w1 = (const float*)d_in[3];
    const float* tm1_b1 = (const float*)d_in[4];
    const float* tm1_w2 = (const float*)d_in[5];
    const float* tm1_b2 = (const float*)d_in[6];
    const float* q_w = (const float*)d_in[7];
    const float* q_b = (const float*)d_in[8];
    const float* k_w = (const float*)d_in[9];
    const float* k_b = (const float*)d_in[10];
    const float* v_w = (const float*)d_in[11];
    const float* v_b = (const float*)d_in[12];
    const float* m1_w = (const float*)d_in[13];
    const float* m1_b = (const float*)d_in[14];
    const float* bn2_g = (const float*)d_in[15];
    const float* bn2_b = (const float*)d_in[16];
    const float* tm2_w1 = (const float*)d_in[17];
    const float* tm2_b1 = (const float*)d_in[18];
    const float* tm2_w2 = (const float*)d_in[19];
    const float* tm2_b2 = (const float*)d_in[20];
    const float* m2_w = (const float*)d_in[21];
    const float* m2_b = (const float*)d_in[22];
    float* out = (float*)d_out;

    float *bnA, *hid, *feat, *q, *k, *v, *E, *Vv, *T, *res, *scale, *shift;
    cudaGetSymbolAddress((void**)&bnA,   g_bnA);
    cudaGetSymbolAddress((void**)&hid,   g_hid);
    cudaGetSymbolAddress((void**)&feat,  g_feat);
    cudaGetSymbolAddress((void**)&q,     g_q);
    cudaGetSymbolAddress((void**)&k,     g_k);
    cudaGetSymbolAddress((void**)&v,     g_v);
    cudaGetSymbolAddress((void**)&E,     g_E);
    cudaGetSymbolAddress((void**)&Vv,    g_V);
    cudaGetSymbolAddress((void**)&T,     g_T);
    cudaGetSymbolAddress((void**)&res,   g_res);
    cudaGetSymbolAddress((void**)&scale, g_scale);
    cudaGetSymbolAddress((void**)&shift, g_shift);

    const long sCN = (long)Cc*Nn;   // per-batch stride of (C,N) tensors
    const long sNN = (long)Nn*Nn;   // per-batch stride of energy

    dim3 gTM(Nn/GBN, (Bn*Cc)/GBM, 1);   // (18, 16, 1)  M=2048 GEMMs
    dim3 gCV(Nn/GBN, 1, Bn);            // (18, 1, 16)  M=128 batched GEMMs
    dim3 blk(256);

    // ---- BN1 + TM1 -> features ----
    bn_stats<<<Cc, 256>>>(front_x, bn1_g, bn1_b, scale, shift);
    bn_apply<<<(unsigned)(BCN/1024), 1024>>>(front_x, scale, shift, bnA);
    gemm_kernel<true,false,true><<<gTM, blk>>>(bnA, tm1_w1, tm1_w1, Nn, tm1_b1, hid,
                                               Bn*Cc, Nn, Nn, 0, 0, 0);
    gemm_kernel<true,false,true><<<gTM, blk>>>(hid, tm1_w2, tm1_w2, Nn, tm1_b2, feat,
                                               Bn*Cc, Nn, Nn, 0, 0, 0);
    // ---- q, k, v projections ----
    qk_kernel<<<dim3(Nn/256, Bn), blk>>>(feat, q_w, q_b, k_w, k_b, q, k);
    gemm_kernel<false,true,false><<<gCV, blk>>>(v_w, feat, feat, Cc, v_b, v,
                                                Cc, Nn, Cc, 0, sCN, sCN);
    // ---- attention ----
    energy_kernel<<<dim3(Nn/64, Nn/64, Bn), blk>>>(k, q, E);
    softmax_rows<<<Bn*Nn, blk>>>(E);
    // V[b,c,i] = sum_j E[b,i,j] * v[b,c,j]  => A=v (128 x 2304), B=E (NT)
    gemm_kernel<true,false,false><<<gCV, blk>>>(v, E, E, Nn, nullptr, Vv,
                                                Cc, Nn, Nn, sCN, sNN, sCN);
    // ---- T = m1_w @ [feat; V] + m1_b ----
    gemm_kernel<false,true,false><<<gCV, blk>>>(m1_w, feat, Vv, Cc, m1_b, T,
                                                Cc, Nn, 2*Cc, 0, sCN, sCN);
    // ---- BN2 + TM2 -> front_res ----
    bn_stats<<<Cc, 256>>>(T, bn2_g, bn2_b, scale, shift);
    bn_apply<<<(unsigned)(BCN/1024), 1024>>>(T, scale, shift, bnA);
    gemm_kernel<true,false,true><<<gTM, blk>>>(bnA, tm2_w1, tm2_w1, Nn, tm2_b1, hid,
                                               Bn*Cc, Nn, Nn, 0, 0, 0);
    gemm_kernel<true,false,true><<<gTM, blk>>>(hid, tm2_w2, tm2_w2, Nn, tm2_b2, res,
                                               Bn*Cc, Nn, Nn, 0, 0, 0);
    // ---- output = m2_w @ [front_res; V] + m2_b ----
    gemm_kernel<false,true,false><<<gCV, blk>>>(m2_w, res, Vv, Cc, m2_b, out,
                                                Cc, Nn, 2*Cc, 0, sCN, sCN);
    (void)in_sizes; (void)n_in; (void)out_size;
}

// round 4
// speedup vs baseline: 1.6891x; 1.6891x over previous
#include <cuda_runtime.h>
#include <cuda_bf16.h>
#include <math.h>
#include <stdint.h>

#define Bn 16
#define Cc 128
#define Pp 48
#define Nn (Pp*Pp)        // 2304
#define C8v 16            // C/8
#define BCN ((long)Bn*Cc*Nn)

// ---------------- scratch (device globals; no allocation allowed) ----------------
__device__ float g_bnA[Bn*Cc*Nn];
__device__ float g_hid[Bn*Cc*Nn];
__device__ float g_feat[Bn*Cc*Nn];
__device__ float g_q[Bn*C8v*Nn];
__device__ float g_k[Bn*C8v*Nn];
__device__ float g_v[Bn*Cc*Nn];
__device__ float g_E[(long)Bn*Nn*Nn]; // 340 MB energy
__device__ float g_V[Bn*Cc*Nn];
__device__ float g_T[Bn*Cc*Nn];
__device__ float g_res[Bn*Cc*Nn];
__device__ float g_scale[Cc], g_shift[Cc];

// ================= helpers =================
__device__ __forceinline__ uint32_t smem_u32(const void* p) {
    uint32_t a;
    asm("{ .reg .u64 t; cvta.to.shared.u64 t, %1; cvt.u32.u64 %0, t; }" : "=r"(a) : "l"(p));
    return a;
}
__device__ __forceinline__ uint16_t f2bf(float x) {
    __nv_bfloat16 b = __float2bfloat16(x);
    return *reinterpret_cast<uint16_t*>(&b);
}
__device__ __forceinline__ float bf2f(uint16_t u) {
    __nv_bfloat16 b;
    *reinterpret_cast<uint16_t*>(&b) = u;
    return __bfloat162float(b);
}

#define LDSM4(r, a) \
    asm volatile("ldmatrix.sync.aligned.m8n8.x4.shared.b16 {%0,%1,%2,%3}, [%4];" \
        : "=r"((r)[0]), "=r"((r)[1]), "=r"((r)[2]), "=r"((r)[3]) : "r"(a))

#define MMA_BF16(d, a, b) \
    asm volatile("mma.sync.aligned.m16n8k16.row.col.f32.bf16.bf16.f32 " \
        "{%0,%1,%2,%3},{%4,%5,%6,%7},{%8,%9},{%0,%1,%2,%3};" \
        : "+f"((d)[0]), "+f"((d)[1]), "+f"((d)[2]), "+f"((d)[3]) \
        : "r"((a)[0]), "r"((a)[1]), "r"((a)[2]), "r"((a)[3]), "r"((b)[0]), "r"((b)[1]))

// ================= mma.sync 3xBF16 NT GEMM =================
// C[m,n] = sum_k A[m,k]*B[n,k] (+bias[n]) (relu)
// A: M x K row-major (batch stride sA); B: Nd x K row-major (stride sB).
// Block tile 128x128, 8 warps (warp tile 32x64), K-chunk 32, 2 SMEM stages.
#define KC 32
#define ROWB 80            // padded row bytes (64B data + 16B pad, conflict-free ldmatrix)
#define ARRB (128*ROWB)    // 10240 bytes per array
#define STGB (4*ARRB)      // Ah|Al|Bh|Bl = 40960
#define MG_SMEM (2*STGB)   // 81920

template<bool BIAS, bool RELU>
__global__ __launch_bounds__(256, 1)
void mma_gemm(const float* __restrict__ A, const float* __restrict__ B,
              const float* __restrict__ bias, float* __restrict__ C,
              int K, int Nd, long sA, long sB, long sC) {
    extern __shared__ char sm[];
    uint32_t sbase = smem_u32(sm);
    int t = threadIdx.x;
    int lane = t & 31, wid = t >> 5;
    int wm = (wid & 3) * 32;       // warp m offset in tile
    int wn = (wid >> 2) * 64;      // warp n offset in tile
    int m0 = blockIdx.y * 128;
    int n0 = blockIdx.x * 128;
    long zb = blockIdx.z;
    const float* Ab = A + zb*sA;
    const float* Bb = B + zb*sB;

    int lr = t >> 1;               // staging row 0..127
    int lc = (t & 1) * 16;         // staging col (floats) 0 or 16

    float acc[2][8][4];
#pragma unroll
    for (int i = 0; i < 2; i++)
#pragma unroll
        for (int j = 0; j < 8; j++)
#pragma unroll
            for (int e = 0; e < 4; e++) acc[i][j][e] = 0.f;

    const int KCH = K / KC;
    float4 ra[4], rb[4];

    // ---- staging helpers ----
#define GLOAD(c) { \
        const float* ap = Ab + (long)(m0 + lr)*K + (c)*KC + lc; \
        const float* bp = Bb + (long)(n0 + lr)*K + (c)*KC + lc; \
        ra[0] = *reinterpret_cast<const float4*>(ap); \
        ra[1] = *reinterpret_cast<const float4*>(ap+4); \
        ra[2] = *reinterpret_cast<const float4*>(ap+8); \
        ra[3] = *reinterpret_cast<const float4*>(ap+12); \
        rb[0] = *reinterpret_cast<const float4*>(bp); \
        rb[1] = *reinterpret_cast<const float4*>(bp+4); \
        rb[2] = *reinterpret_cast<const float4*>(bp+8); \
        rb[3] = *reinterpret_cast<const float4*>(bp+12); \
    }

#define CVSTORE(s) { \
        char* base = sm + (s)*STGB + lr*ROWB + lc*2; \
        uint32_t ph[8], pl[8]; \
        const float* fa = reinterpret_cast<const float*>(ra); \
_Pragma("unroll") \
        for (int j = 0; j < 8; j++) { \
            float x0 = fa[2*j], x1 = fa[2*j+1]; \
            uint16_t h0 = f2bf(x0), h1 = f2bf(x1); \
            uint16_t l0 = f2bf(x0 - bf2f(h0)), l1 = f2bf(x1 - bf2f(h1)); \
            ph[j] = (uint32_t)h0 | ((uint32_t)h1 << 16); \
            pl[j] = (uint32_t)l0 | ((uint32_t)l1 << 16); \
        } \
        reinterpret_cast<uint4*>(base)[0]        = make_uint4(ph[0],ph[1],ph[2],ph[3]); \
        reinterpret_cast<uint4*>(base + 16)[0]   = make_uint4(ph[4],ph[5],ph[6],ph[7]); \
        reinterpret_cast<uint4*>(base + ARRB)[0]      = make_uint4(pl[0],pl[1],pl[2],pl[3]); \
        reinterpret_cast<uint4*>(base + ARRB + 16)[0] = make_uint4(pl[4],pl[5],pl[6],pl[7]); \
        const float* fb = reinterpret_cast<const float*>(rb); \
_Pragma("unroll") \
        for (int j = 0; j < 8; j++) { \
            float x0 = fb[2*j], x1 = fb[2*j+1]; \
            uint16_t h0 = f2bf(x0), h1 = f2bf(x1); \
            uint16_t l0 = f2bf(x0 - bf2f(h0)), l1 = f2bf(x1 - bf2f(h1)); \
            ph[j] = (uint32_t)h0 | ((uint32_t)h1 << 16); \
            pl[j] = (uint32_t)l0 | ((uint32_t)l1 << 16); \
        } \
        reinterpret_cast<uint4*>(base + 2*ARRB)[0]      = make_uint4(ph[0],ph[1],ph[2],ph[3]); \
        reinterpret_cast<uint4*>(base + 2*ARRB + 16)[0] = make_uint4(ph[4],ph[5],ph[6],ph[7]); \
        reinterpret_cast<uint4*>(base + 3*ARRB)[0]      = make_uint4(pl[0],pl[1],pl[2],pl[3]); \
        reinterpret_cast<uint4*>(base + 3*ARRB + 16)[0] = make_uint4(pl[4],pl[5],pl[6],pl[7]); \
    }

    // prologue: stage chunk 0
    GLOAD(0);
    CVSTORE(0);
    __syncthreads();

    for (int c = 0; c < KCH; c++) {
        bool more = (c + 1 < KCH);
        if (more) GLOAD(c + 1);

        uint32_t stA  = sbase + (uint32_t)(c & 1)*STGB;
        uint32_t stAl = stA + ARRB;
        uint32_t stB  = stA + 2*ARRB;
        uint32_t stBl = stA + 3*ARRB;

#pragma unroll
        for (int k16 = 0; k16 < 2; k16++) {
            uint32_t a_h[2][4], a_l[2][4];
#pragma unroll
            for (int im = 0; im < 2; im++) {
                uint32_t off = (uint32_t)(wm + im*16 + (lane & 15))*ROWB
                             + k16*32 + ((lane >> 4) & 1)*16;
                LDSM4(a_h[im], stA  + off);
                LDSM4(a_l[im], stAl + off);
            }
            uint32_t b_h[8][2], b_l[8][2];
#pragma unroll
            for (int jp = 0; jp < 4; jp++) {
                int g = lane >> 3;
                uint32_t off = (uint32_t)(wn + jp*16 + (g >> 1)*8 + (lane & 7))*ROWB
                             + k16*32 + (g & 1)*16;
                uint32_t r[4];
                LDSM4(r, stB + off);
                b_h[2*jp][0] = r[0]; b_h[2*jp][1] = r[1];
                b_h[2*jp+1][0] = r[2]; b_h[2*jp+1][1] = r[3];
                LDSM4(r, stBl + off);
                b_l[2*jp][0] = r[0]; b_l[2*jp][1] = r[1];
                b_l[2*jp+1][0] = r[2]; b_l[2*jp+1][1] = r[3];
            }
#pragma unroll
            for (int im = 0; im < 2; im++)
#pragma unroll
                for (int jn = 0; jn < 8; jn++) {
                    MMA_BF16(acc[im][jn], a_h[im], b_h[jn]);
                    MMA_BF16(acc[im][jn], a_h[im], b_l[jn]);
                    MMA_BF16(acc[im][jn], a_l[im], b_h[jn]);
                }
        }
        if (more) CVSTORE((c + 1) & 1);
        __syncthreads();
    }
#undef GLOAD
#undef CVSTORE

    // ---- epilogue ----
    int r0 = lane >> 2;
    int cc = (lane & 3) * 2;
#pragma unroll
    for (int im = 0; im < 2; im++) {
#pragma unroll
        for (int jn = 0; jn < 8; jn++) {
            int m = m0 + wm + im*16 + r0;
            int n = n0 + wn + jn*8 + cc;
            float b0 = 0.f, b1 = 0.f;
            if (BIAS) { b0 = bias[n]; b1 = bias[n+1]; }
            float2 v0, v1;
            v0.x = acc[im][jn][0] + b0; v0.y = acc[im][jn][1] + b1;
            v1.x = acc[im][jn][2] + b0; v1.y = acc[im][jn][3] + b1;
            if (RELU) {
                v0.x = fmaxf(v0.x, 0.f); v0.y = fmaxf(v0.y, 0.f);
                v1.x = fmaxf(v1.x, 0.f); v1.y = fmaxf(v1.y, 0.f);
            }
            *reinterpret_cast<float2*>(C + zb*sC + (long)m*Nd + n)     = v0;
            *reinterpret_cast<float2*>(C + zb*sC + (long)(m+8)*Nd + n) = v1;
        }
    }
}

// ---------------- BN ----------------
__global__ void bn_stats(const float* __restrict__ x, const float* __restrict__ g,
                         const float* __restrict__ b, float* __restrict__ scale,
                         float* __restrict__ shift) {
    int c = blockIdx.x;
    int tid = threadIdx.x;
    double s = 0.0, sq = 0.0;
    for (int idx = tid; idx < Bn*Nn; idx += blockDim.x) {
        int bb = idx / Nn, n = idx - bb*Nn;
        float v = x[((long)bb*Cc + c)*Nn + n];
        s += v; sq += (double)v * v;
    }
    __shared__ double sh_s[256], sh_q[256];
    sh_s[tid] = s; sh_q[tid] = sq; __syncthreads();
    for (int off = 128; off; off >>= 1) {
        if (tid < off) { sh_s[tid] += sh_s[tid+off]; sh_q[tid] += sh_q[tid+off]; }
        __syncthreads();
    }
    if (tid == 0) {
        double inv = 1.0 / (double)(Bn*Nn);
        double mean = sh_s[0] * inv;
        double var  = sh_q[0] * inv - mean*mean;
        float sc = g[c] * rsqrtf((float)var + 1e-5f);
        scale[c] = sc;
        shift[c] = b[c] - (float)mean * sc;
    }
}

__global__ void bn_apply(const float* __restrict__ x, const float* __restrict__ scale,
                         const float* __restrict__ shift, float* __restrict__ y) {
    long i = (long)blockIdx.x * blockDim.x + threadIdx.x;
    if (i < BCN) {
        int c = (int)((i / Nn) % Cc);
        y[i] = x[i] * scale[c] + shift[c];
    }
}

// ---------------- fp32 NN SGEMM (channel convs; M=128, K<=256) ----------------
#define GBM 128
#define GBN 128
#define GBK 16

template<bool BIASROW, bool RELU>
__global__ __launch_bounds__(256, 1)
void gemm_nn(const float* __restrict__ A,
             const float* __restrict__ B1, const float* __restrict__ B2, int K1,
             const float* __restrict__ bias, float* __restrict__ C,
             int Nd, int K, long sB, long sC) {
    __shared__ float As[GBK][GBM];
    __shared__ float Bs[GBK][GBN];
    int tid = threadIdx.x;
    int m0 = blockIdx.y * GBM;
    int n0 = blockIdx.x * GBN;
    long zb = blockIdx.z;
    const float* B1b = B1 + zb*sB;
    const float* B2b = B2 + zb*sB;

    float acc[8][8];
#pragma unroll
    for (int i = 0; i < 8; i++)
#pragma unroll
        for (int j = 0; j < 8; j++) acc[i][j] = 0.f;

    int ar = tid >> 2;
    int ac = (tid & 3) * 4;
    int tm = (tid >> 4) * 8;
    int tn = (tid & 15) * 8;

    for (int k0 = 0; k0 < K; k0 += GBK) {
#pragma unroll
        for (int r = 0; r < 2; r++) {
            int rw = ar + 64*r;
            float4 av = *reinterpret_cast<const float4*>(A + (long)(m0+rw)*K + k0 + ac);
            As[ac+0][rw] = av.x; As[ac+1][rw] = av.y;
            As[ac+2][rw] = av.z; As[ac+3][rw] = av.w;
        }
#pragma unroll
        for (int r = 0; r < 2; r++) {
            int s  = tid + 256*r;
            int kk = s >> 5;
            int nq = (s & 31) * 4;
            int kg = k0 + kk;
            const float* Bp = (kg < K1) ? (B1b + (long)kg*Nd)
                                        : (B2b + (long)(kg-K1)*Nd);
            *reinterpret_cast<float4*>(&Bs[kk][nq]) =
                *reinterpret_cast<const float4*>(Bp + n0 + nq);
        }
        __syncthreads();
#pragma unroll
        for (int kk = 0; kk < GBK; kk++) {
            float a[8], b[8];
            float4 a0 = *reinterpret_cast<const float4*>(&As[kk][tm]);
            float4 a1 = *reinterpret_cast<const float4*>(&As[kk][tm+4]);
            float4 b0 = *reinterpret_cast<const float4*>(&Bs[kk][tn]);
            float4 b1 = *reinterpret_cast<const float4*>(&Bs[kk][tn+4]);
            a[0]=a0.x;a[1]=a0.y;a[2]=a0.z;a[3]=a0.w;a[4]=a1.x;a[5]=a1.y;a[6]=a1.z;a[7]=a1.w;
            b[0]=b0.x;b[1]=b0.y;b[2]=b0.z;b[3]=b0.w;b[4]=b1.x;b[5]=b1.y;b[6]=b1.z;b[7]=b1.w;
#pragma unroll
            for (int i = 0; i < 8; i++)
#pragma unroll
                for (int j = 0; j < 8; j++)
                    acc[i][j] = fmaf(a[i], b[j], acc[i][j]);
        }
        __syncthreads();
    }
    int gm = m0 + tm, gn = n0 + tn;
#pragma unroll
    for (int i = 0; i < 8; i++) {
#pragma unroll
        for (int j = 0; j < 8; j++) {
            float v = acc[i][j];
            if (bias) v += BIASROW ? bias[gm+i] : bias[gn+j];
            if (RELU) v = fmaxf(v, 0.f);
            C[zb*sC + (long)(gm+i)*Nd + gn + j] = v;
        }
    }
}

// ---------------- q & k projection ----------------
__global__ __launch_bounds__(256)
void qk_kernel(const float* __restrict__ feat,
               const float* __restrict__ qw, const float* __restrict__ qb,
               const float* __restrict__ kw, const float* __restrict__ kb,
               float* __restrict__ q, float* __restrict__ k) {
    __shared__ float wq[C8v*Cc], wk[C8v*Cc];
    int tid = threadIdx.x;
    for (int i = tid; i < C8v*Cc; i += 256) { wq[i] = qw[i]; wk[i] = kw[i]; }
    __syncthreads();
    int b = blockIdx.y;
    int n = blockIdx.x * 256 + tid;
    const float* f = feat + (long)b*Cc*Nn + n;
    float aq[C8v], ak[C8v];
#pragma unroll
    for (int o = 0; o < C8v; o++) { aq[o] = qb[o]; ak[o] = kb[o]; }
    for (int c = 0; c < Cc; c++) {
        float fv = f[(long)c*Nn];
#pragma unroll
        for (int o = 0; o < C8v; o++) {
            aq[o] = fmaf(wq[o*Cc+c], fv, aq[o]);
            ak[o] = fmaf(wk[o*Cc+c], fv, ak[o]);
        }
    }
#pragma unroll
    for (int o = 0; o < C8v; o++) {
        q[((long)b*C8v+o)*Nn + n] = aq[o];
        k[((long)b*C8v+o)*Nn + n] = ak[o];
    }
}

// ---------------- energy ----------------
__global__ __launch_bounds__(256)
void energy_kernel(const float* __restrict__ K_, const float* __restrict__ Q_,
                   float* __restrict__ E) {
    __shared__ float ks[C8v][64], qs[C8v][64];
    int b  = blockIdx.z;
    int i0 = blockIdx.y * 64, j0 = blockIdx.x * 64;
    int tid = threadIdx.x;
    const float* Kb = K_ + (long)b*C8v*Nn;
    const float* Qb = Q_ + (long)b*C8v*Nn;
    for (int s = tid; s < C8v*64; s += 256) {
        int c = s >> 6, x = s & 63;
        ks[c][x] = Kb[(long)c*Nn + i0 + x];
        qs[c][x] = Qb[(long)c*Nn + j0 + x];
    }
    __syncthreads();
    int ri = (tid >> 4) * 4, rj = (tid & 15) * 4;
    float acc[4][4] = {};
#pragma unroll
    for (int c = 0; c < C8v; c++) {
        float a[4], bb[4];
#pragma unroll
        for (int i = 0; i < 4; i++) a[i]  = ks[c][ri+i];
#pragma unroll
        for (int j = 0; j < 4; j++) bb[j] = qs[c][rj+j];
#pragma unroll
        for (int i = 0; i < 4; i++)
#pragma unroll
            for (int j = 0; j < 4; j++)
                acc[i][j] = fmaf(a[i], bb[j], acc[i][j]);
    }
    const float sc = 0.08838834764831845f;  // 1/sqrt(128)
    float* Eb = E + ((long)b*Nn + i0) * Nn + j0;
#pragma unroll
    for (int i = 0; i < 4; i++)
#pragma unroll
        for (int j = 0; j < 4; j++)
            Eb[(long)(ri+i)*Nn + rj + j] = acc[i][j] * sc;
}

// ---------------- row softmax ----------------
__global__ __launch_bounds__(256)
void softmax_rows(float* __restrict__ E) {
    const int T = 256, PER = Nn / T;  // 9
    long rowi = blockIdx.x;
    float* p = E + rowi * (long)Nn;
    int tid = threadIdx.x;
    float v[PER];
    float m = -1e30f;
#pragma unroll
    for (int i = 0; i < PER; i++) { v[i] = p[tid + i*T]; m = fmaxf(m, v[i]); }
    __shared__ float red[8];
    __shared__ float bc;
#pragma unroll
    for (int o = 16; o; o >>= 1) m = fmaxf(m, __shfl_xor_sync(0xffffffffu, m, o));
    if ((tid & 31) == 0) red[tid >> 5] = m;
    __syncthreads();
    if (tid == 0) {
        float t2 = red[0];
        for (int i = 1; i < 8; i++) t2 = fmaxf(t2, red[i]);
        bc = t2;
    }
    __syncthreads();
    m = bc;
    float s = 0.f;
#pragma unroll
    for (int i = 0; i < PER; i++) { v[i] = __expf(v[i] - m); s += v[i]; }
#pragma unroll
    for (int o = 16; o; o >>= 1) s += __shfl_xor_sync(0xffffffffu, s, o);
    if ((tid & 31) == 0) red[tid >> 5] = s;
    __syncthreads();
    if (tid == 0) {
        float t2 = 0.f;
        for (int i = 0; i < 8; i++) t2 += red[i];
        bc = 1.f / t2;
    }
    __syncthreads();
    float inv = bc;
#pragma unroll
    for (int i = 0; i < PER; i++) p[tid + i*T] = v[i] * inv;
}

// ---------------- launcher ----------------
extern "C" void kernel_launch(void* const* d_in, const int* in_sizes, int n_in,
                              void* d_out, int out_size) {
    const float* front_x = (const float*)d_in[0];
    const float* bn1_g = (const float*)d_in[1];
    const float* bn1_b = (const float*)d_in[2];
    const float* tm1_w1 = (const float*)d_in[3];
    const float* tm1_b1 = (const float*)d_in[4];
    const float* tm1_w2 = (const float*)d_in[5];
    const float* tm1_b2 = (const float*)d_in[6];
    const float* q_w = (const float*)d_in[7];
    const float* q_b = (const float*)d_in[8];
    const float* k_w = (const float*)d_in[9];
    const float* k_b = (const float*)d_in[10];
    const float* v_w = (const float*)d_in[11];
    const float* v_b = (const float*)d_in[12];
    const float* m1_w = (const float*)d_in[13];
    const float* m1_b = (const float*)d_in[14];
    const float* bn2_g = (const float*)d_in[15];
    const float* bn2_b = (const float*)d_in[16];
    const float* tm2_w1 = (const float*)d_in[17];
    const float* tm2_b1 = (const float*)d_in[18];
    const float* tm2_w2 = (const float*)d_in[19];
    const float* tm2_b2 = (const float*)d_in[20];
    const float* m2_w = (const float*)d_in[21];
    const float* m2_b = (const float*)d_in[22];
    float* out = (float*)d_out;

    float *bnA, *hid, *feat, *q, *k, *v, *E, *Vv, *T, *res, *scale, *shift;
    cudaGetSymbolAddress((void**)&bnA,   g_bnA);
    cudaGetSymbolAddress((void**)&hid,   g_hid);
    cudaGetSymbolAddress((void**)&feat,  g_feat);
    cudaGetSymbolAddress((void**)&q,     g_q);
    cudaGetSymbolAddress((void**)&k,     g_k);
    cudaGetSymbolAddress((void**)&v,     g_v);
    cudaGetSymbolAddress((void**)&E,     g_E);
    cudaGetSymbolAddress((void**)&Vv,    g_V);
    cudaGetSymbolAddress((void**)&T,     g_T);
    cudaGetSymbolAddress((void**)&res,   g_res);
    cudaGetSymbolAddress((void**)&scale, g_scale);
    cudaGetSymbolAddress((void**)&shift, g_shift);

    cudaFuncSetAttribute(mma_gemm<true,true>,   cudaFuncAttributeMaxDynamicSharedMemorySize, MG_SMEM);
    cudaFuncSetAttribute(mma_gemm<false,false>, cudaFuncAttributeMaxDynamicSharedMemorySize, MG_SMEM);

    const long sCN = (long)Cc*Nn;
    const long sNN = (long)Nn*Nn;

    dim3 gTM(Nn/128, (Bn*Cc)/128, 1);   // (18, 16, 1)
    dim3 gPV(Nn/128, 1, Bn);            // (18, 1, 16)
    dim3 gCV(Nn/GBN, 1, Bn);

    // ---- BN1 + TM1 -> features ----
    bn_stats<<<Cc, 256>>>(front_x, bn1_g, bn1_b, scale, shift);
    bn_apply<<<(unsigned)(BCN/1024), 1024>>>(front_x, scale, shift, bnA);
    mma_gemm<true,true><<<gTM, 256, MG_SMEM>>>(bnA, tm1_w1, tm1_b1, hid, Nn, Nn, 0, 0, 0);
    mma_gemm<true,true><<<gTM, 256, MG_SMEM>>>(hid, tm1_w2, tm1_b2, feat, Nn, Nn, 0, 0, 0);
    // ---- q, k, v projections ----
    qk_kernel<<<dim3(Nn/256, Bn), 256>>>(feat, q_w, q_b, k_w, k_b, q, k);
    gemm_nn<true,false><<<gCV, 256>>>(v_w, feat, feat, Cc, v_b, v, Nn, Cc, sCN, sCN);
    // ---- attention ----
    energy_kernel<<<dim3(Nn/64, Nn/64, Bn), 256>>>(k, q, E);
    softmax_rows<<<Bn*Nn, 256>>>(E);
    // V[b,c,i] = sum_j E[b,i,j] * v[b,c,j]  -> mma NT, batched
    mma_gemm<false,false><<<gPV, 256, MG_SMEM>>>(v, E, nullptr, Vv, Nn, Nn, sCN, sNN, sCN);
    // ---- T = m1_w @ [feat; V] + m1_b ----
    gemm_nn<true,false><<<gCV, 256>>>(m1_w, feat, Vv, Cc, m1_b, T, Nn, 2*Cc, sCN, sCN);
    // ---- BN2 + TM2 -> front_res ----
    bn_stats<<<Cc, 256>>>(T, bn2_g, bn2_b, scale, shift);
    bn_apply<<<(unsigned)(BCN/1024), 1024>>>(T, scale, shift, bnA);
    mma_gemm<true,true><<<gTM, 256, MG_SMEM>>>(bnA, tm2_w1, tm2_b1, hid, Nn, Nn, 0, 0, 0);
    mma_gemm<true,true><<<gTM, 256, MG_SMEM>>>(hid, tm2_w2, tm2_b2, res, Nn, Nn, 0, 0, 0);
    // ---- output = m2_w @ [front_res; V] + m2_b ----
    gemm_nn<true,false><<<gCV, 256>>>(m2_w, res, Vv, Cc, m2_b, out, Nn, 2*Cc, sCN, sCN);
    (void)in_sizes; (void)n_in; (void)out_size;
}